// round 3
// baseline (speedup 1.0000x reference)
#include <cuda_runtime.h>
#include <math.h>

#define NPTS 16384
#define KNB  16

// ---------------- device scratch (static: no allocations allowed) ----------------
__device__ float d_geo[NPTS * 4];            // mean geometric feature per point
__device__ int   d_knn32[NPTS * KNB];        // int32 copy of knn
__device__ int   d_knn_is64;                 // dtype detection flag
__device__ float d_G1[NPTS * 128];           // geo_mean @ w_lfa1^T + b_lfa1
__device__ float d_Gcat[(size_t)NPTS * 384]; // [G2 (256) | A(G1) (128)]
__device__ float d_C0[(size_t)NPTS * 512];   // block-invariant part of mlp2 output
__device__ float d_fa[(size_t)NPTS * 512];   // ping
__device__ float d_fb[(size_t)NPTS * 512];   // pong
__device__ float d_xr[(size_t)NPTS * 640];   // [x1 (128) | f0 @ w_res^T (512)]
__device__ float d_ax1[NPTS * 128];          // A(x1)
__device__ float d_aax1[NPTS * 128];         // A(A(x1))
__device__ float d_dv[512];                  // W2[:,384:512] @ b_mlp1
__device__ float d_bsum[512];                // b_mlp2 + b_res

// ---------------- knn dtype detection (int64 vs int32) ----------------
// Reads the first NPTS*KNB/2 8-byte words — safe whether the buffer holds
// int64 (2 MB) or int32 (1 MB) elements. True int64 data: every word is a
// valid index in [0, NPTS). int32 data: words are (lo + hi*2^32), out of
// range whenever hi != 0 (prob 1 - 1/NPTS per word).
__global__ void k_detect(const void* __restrict__ knn) {
    __shared__ int bad;
    if (threadIdx.x == 0) bad = 0;
    __syncthreads();
    const long long* p = (const long long*)knn;
    const int total = NPTS * KNB / 2;
    int local = 0;
    for (int i = threadIdx.x; i < total; i += blockDim.x) {
        long long v = p[i];
        if (v < 0 || v >= NPTS) local = 1;
    }
    if (local) atomicOr(&bad, 1);
    __syncthreads();
    if (threadIdx.x == 0) d_knn_is64 = bad ? 0 : 1;
}

// ---------------- convert knn -> int32 (branch on detected dtype) ----------------
__global__ void k_cvt(const void* __restrict__ knn) {
    int i = blockIdx.x * blockDim.x + threadIdx.x;
    if (i >= NPTS * KNB) return;
    if (d_knn_is64)
        d_knn32[i] = (int)((const long long*)knn)[i];
    else
        d_knn32[i] = ((const int*)knn)[i];
}

// ---------------- prep: geo mean ----------------
__global__ void k_prep(const float* __restrict__ inp) {
    int n = blockIdx.x * blockDim.x + threadIdx.x;
    if (n >= NPTS) return;
    float xi = inp[3 * n + 0], yi = inp[3 * n + 1], zi = inp[3 * n + 2];
    float sx = 0.f, sy = 0.f, sz = 0.f, sn = 0.f;
#pragma unroll
    for (int k = 0; k < KNB; k++) {
        int j = d_knn32[n * KNB + k];
        float dx = xi - inp[3 * j + 0];
        float dy = yi - inp[3 * j + 1];
        float dz = zi - inp[3 * j + 2];
        float nm = sqrtf(dx * dx + dy * dy + dz * dz);
        sx += dx; sy += dy; sz += dz; sn += nm;
    }
    const float s = 1.0f / KNB;
    d_geo[n * 4 + 0] = sx * s;
    d_geo[n * 4 + 1] = sy * s;
    d_geo[n * 4 + 2] = sz * s;
    d_geo[n * 4 + 3] = sn * s;
}

// ---------------- tiny geo linears + tiny vectors ----------------
// blocks [0 .. NPTS*96/256): G2 -> Gcat[:, :256], G1 -> d_G1
// last block: d_bsum, d_dv
__global__ void k_smallg(const float* __restrict__ w_lfa1, const float* __restrict__ b_lfa1,
                         const float* __restrict__ w_lfa2, const float* __restrict__ b_lfa2,
                         const float* __restrict__ w_mlp2, const float* __restrict__ b_mlp1,
                         const float* __restrict__ b_mlp2, const float* __restrict__ b_res) {
    int idx = blockIdx.x * blockDim.x + threadIdx.x;
    if (idx >= NPTS * 96) {
        int j = (idx - NPTS * 96) * 2;
        if (j < 512) {
#pragma unroll
            for (int t = 0; t < 2; t++) {
                int jj = j + t;
                d_bsum[jj] = b_mlp2[jj] + b_res[jj];
                float s = 0.f;
#pragma unroll 8
                for (int c = 0; c < 128; c++) s += w_mlp2[jj * 512 + 384 + c] * b_mlp1[c];
                d_dv[jj] = s;
            }
        }
        return;
    }
    int n = idx / 96;
    int j0 = (idx % 96) * 4;
    float g0 = d_geo[n * 4 + 0], g1 = d_geo[n * 4 + 1];
    float g2 = d_geo[n * 4 + 2], g3 = d_geo[n * 4 + 3];
    float r[4];
    if (j0 < 256) {
#pragma unroll
        for (int t = 0; t < 4; t++) {
            int j = j0 + t;
            r[t] = b_lfa2[j] + g0 * w_lfa2[j * 4 + 0] + g1 * w_lfa2[j * 4 + 1]
                             + g2 * w_lfa2[j * 4 + 2] + g3 * w_lfa2[j * 4 + 3];
        }
        *(float4*)(d_Gcat + (size_t)n * 384 + j0) = make_float4(r[0], r[1], r[2], r[3]);
    } else {
        int jj0 = j0 - 256;
#pragma unroll
        for (int t = 0; t < 4; t++) {
            int j = jj0 + t;
            r[t] = b_lfa1[j] + g0 * w_lfa1[j * 4 + 0] + g1 * w_lfa1[j * 4 + 1]
                             + g2 * w_lfa1[j * 4 + 2] + g3 * w_lfa1[j * 4 + 3];
        }
        *(float4*)(d_G1 + (size_t)n * 128 + jj0) = make_float4(r[0], r[1], r[2], r[3]);
    }
}

// ---------------- gather-mean (d = 128), one warp per point ----------------
// mode 0: d_G1 (ld 128)  -> d_Gcat cols [256:384] (ld 384)
// mode 1: d_xr  (ld 640) -> d_ax1  (ld 128)   [x1 lives in cols 0:128 of xr]
// mode 2: d_ax1 (ld 128) -> d_aax1 (ld 128)
__global__ void __launch_bounds__(256) k_gather(int mode) {
    int t = blockIdx.x * blockDim.x + threadIdx.x;
    int n = t >> 5;
    if (n >= NPTS) return;
    int lane = t & 31;
    const float* src; float* dst; int sld, dld, doff;
    if (mode == 0)      { src = d_G1;  sld = 128; dst = d_Gcat; dld = 384; doff = 256; }
    else if (mode == 1) { src = d_xr;  sld = 640; dst = d_ax1;  dld = 128; doff = 0; }
    else                { src = d_ax1; sld = 128; dst = d_aax1; dld = 128; doff = 0; }
    const int* kn = d_knn32 + n * KNB;
    float ax = 0.f, ay = 0.f, az = 0.f, aw = 0.f;
#pragma unroll
    for (int k = 0; k < KNB; k++) {
        int j = kn[k];
        float4 v = *(const float4*)(src + (size_t)j * sld + lane * 4);
        ax += v.x; ay += v.y; az += v.z; aw += v.w;
    }
    const float s = 1.0f / KNB;
    *(float4*)(dst + (size_t)n * dld + doff + lane * 4) =
        make_float4(ax * s, ay * s, az * s, aw * s);
}

// ---------------- shared fp32 GEMM core: 128x128 tile, BK=16, 256 threads ----------------
__device__ __forceinline__ void gemm_body(const float* __restrict__ A, int lda,
                                          const float* __restrict__ B, int ldb,
                                          int K, float (&acc)[8][8]) {
    __shared__ float As[16 * 128];
    __shared__ float Bs[16 * 128];
    const int tid  = threadIdx.x;
    const int lrow = tid >> 1;
    const int lcol = (tid & 1) * 8;
    const int tx   = tid & 15;
    const int ty   = tid >> 4;
    const float* Ap = A + (size_t)lrow * lda + lcol;
    const float* Bp = B + (size_t)lrow * ldb + lcol;
    for (int kt = 0; kt < K; kt += 16) {
        float4 a0 = *(const float4*)(Ap + kt);
        float4 a1 = *(const float4*)(Ap + kt + 4);
        float4 b0 = *(const float4*)(Bp + kt);
        float4 b1 = *(const float4*)(Bp + kt + 4);
        __syncthreads();
        As[(lcol + 0) * 128 + lrow] = a0.x;
        As[(lcol + 1) * 128 + lrow] = a0.y;
        As[(lcol + 2) * 128 + lrow] = a0.z;
        As[(lcol + 3) * 128 + lrow] = a0.w;
        As[(lcol + 4) * 128 + lrow] = a1.x;
        As[(lcol + 5) * 128 + lrow] = a1.y;
        As[(lcol + 6) * 128 + lrow] = a1.z;
        As[(lcol + 7) * 128 + lrow] = a1.w;
        Bs[(lcol + 0) * 128 + lrow] = b0.x;
        Bs[(lcol + 1) * 128 + lrow] = b0.y;
        Bs[(lcol + 2) * 128 + lrow] = b0.z;
        Bs[(lcol + 3) * 128 + lrow] = b0.w;
        Bs[(lcol + 4) * 128 + lrow] = b1.x;
        Bs[(lcol + 5) * 128 + lrow] = b1.y;
        Bs[(lcol + 6) * 128 + lrow] = b1.z;
        Bs[(lcol + 7) * 128 + lrow] = b1.w;
        __syncthreads();
#pragma unroll
        for (int k = 0; k < 16; k++) {
            float4 ra0 = *(const float4*)(&As[k * 128 + ty * 8]);
            float4 ra1 = *(const float4*)(&As[k * 128 + ty * 8 + 4]);
            float4 rb0 = *(const float4*)(&Bs[k * 128 + tx * 8]);
            float4 rb1 = *(const float4*)(&Bs[k * 128 + tx * 8 + 4]);
            float ra[8] = {ra0.x, ra0.y, ra0.z, ra0.w, ra1.x, ra1.y, ra1.z, ra1.w};
            float rb[8] = {rb0.x, rb0.y, rb0.z, rb0.w, rb1.x, rb1.y, rb1.z, rb1.w};
#pragma unroll
            for (int i = 0; i < 8; i++)
#pragma unroll
                for (int j = 0; j < 8; j++)
                    acc[i][j] = fmaf(ra[i], rb[j], acc[i][j]);
        }
    }
}

// ---------------- GEMM C0: Gcat[N,384] @ W2[:, :384]^T + bsum ; also fa = C0 + dv ----------------
__global__ void __launch_bounds__(256, 2) k_gemmC0(const float* __restrict__ w_mlp2) {
    float acc[8][8] = {};
    gemm_body(d_Gcat + (size_t)blockIdx.x * 128 * 384, 384,
              w_mlp2 + (size_t)blockIdx.y * 128 * 512, 512, 384, acc);
    const int tx = threadIdx.x & 15, ty = threadIdx.x >> 4;
    const int row0 = blockIdx.x * 128 + ty * 8;
    const int col0 = blockIdx.y * 128 + tx * 8;
    float bs[8], dv[8];
#pragma unroll
    for (int j = 0; j < 8; j++) { bs[j] = d_bsum[col0 + j]; dv[j] = d_dv[col0 + j]; }
#pragma unroll
    for (int i = 0; i < 8; i++) {
        size_t o = (size_t)(row0 + i) * 512 + col0;
        float c[8];
#pragma unroll
        for (int j = 0; j < 8; j++) c[j] = acc[i][j] + bs[j];
        *(float4*)(d_C0 + o)     = make_float4(c[0], c[1], c[2], c[3]);
        *(float4*)(d_C0 + o + 4) = make_float4(c[4], c[5], c[6], c[7]);
        *(float4*)(d_fa + o)     = make_float4(c[0] + dv[0], c[1] + dv[1], c[2] + dv[2], c[3] + dv[3]);
        *(float4*)(d_fa + o + 4) = make_float4(c[4] + dv[4], c[5] + dv[5], c[6] + dv[6], c[7] + dv[7]);
    }
}

// ---------------- GEMM1: xr = f @ [w_mlp1 ; w_res]^T  (N=640, K=512) ----------------
__global__ void __launch_bounds__(256, 2) k_gemm1(int fsel,
        const float* __restrict__ w_mlp1, const float* __restrict__ b_mlp1,
        const float* __restrict__ w_res) {
    const float* f = fsel ? d_fb : d_fa;
    const float* B = (blockIdx.y == 0) ? w_mlp1
                                       : (w_res + (size_t)(blockIdx.y - 1) * 128 * 512);
    float acc[8][8] = {};
    gemm_body(f + (size_t)blockIdx.x * 128 * 512, 512, B, 512, 512, acc);
    const int tx = threadIdx.x & 15, ty = threadIdx.x >> 4;
    const int row0 = blockIdx.x * 128 + ty * 8;
    const int col0 = blockIdx.y * 128 + tx * 8;
    float bias[8];
    if (blockIdx.y == 0) {
#pragma unroll
        for (int j = 0; j < 8; j++) bias[j] = b_mlp1[tx * 8 + j];
    } else {
#pragma unroll
        for (int j = 0; j < 8; j++) bias[j] = 0.f;
    }
#pragma unroll
    for (int i = 0; i < 8; i++) {
        float* o = d_xr + (size_t)(row0 + i) * 640 + col0;
        *(float4*)(o)     = make_float4(acc[i][0] + bias[0], acc[i][1] + bias[1],
                                        acc[i][2] + bias[2], acc[i][3] + bias[3]);
        *(float4*)(o + 4) = make_float4(acc[i][4] + bias[4], acc[i][5] + bias[5],
                                        acc[i][6] + bias[6], acc[i][7] + bias[7]);
    }
}

// ---------------- GEMM2: f_new = C0 + f + r + aax1 @ W2[:,384:512]^T  (K=128) ----------------
__global__ void __launch_bounds__(256, 2) k_gemm2(int fsel, int dsel,
        const float* __restrict__ w_mlp2, float* __restrict__ outp) {
    const float* f = fsel ? d_fb : d_fa;
    float* dst = (dsel == 0) ? d_fb : (dsel == 1) ? d_fa : outp;
    float acc[8][8] = {};
    gemm_body(d_aax1 + (size_t)blockIdx.x * 128 * 128, 128,
              w_mlp2 + (size_t)blockIdx.y * 128 * 512 + 384, 512, 128, acc);
    const int tx = threadIdx.x & 15, ty = threadIdx.x >> 4;
    const int row0 = blockIdx.x * 128 + ty * 8;
    const int col0 = blockIdx.y * 128 + tx * 8;
#pragma unroll
    for (int i = 0; i < 8; i++) {
        int row = row0 + i;
        size_t o512 = (size_t)row * 512 + col0;
        float4 c0a = *(const float4*)(d_C0 + o512);
        float4 c0b = *(const float4*)(d_C0 + o512 + 4);
        float4 fa_ = *(const float4*)(f + o512);
        float4 fb_ = *(const float4*)(f + o512 + 4);
        float4 ra  = *(const float4*)(d_xr + (size_t)row * 640 + 128 + col0);
        float4 rb  = *(const float4*)(d_xr + (size_t)row * 640 + 128 + col0 + 4);
        float4 v0 = make_float4(acc[i][0] + c0a.x + fa_.x + ra.x,
                                acc[i][1] + c0a.y + fa_.y + ra.y,
                                acc[i][2] + c0a.z + fa_.z + ra.z,
                                acc[i][3] + c0a.w + fa_.w + ra.w);
        float4 v1 = make_float4(acc[i][4] + c0b.x + fb_.x + rb.x,
                                acc[i][5] + c0b.y + fb_.y + rb.y,
                                acc[i][6] + c0b.z + fb_.z + rb.z,
                                acc[i][7] + c0b.w + fb_.w + rb.w);
        *(float4*)(dst + o512)     = v0;
        *(float4*)(dst + o512 + 4) = v1;
    }
}

// ---------------- launch ----------------
extern "C" void kernel_launch(void* const* d_in, const int* in_sizes, int n_in,
                              void* d_out, int out_size) {
    const float* inputs = (const float*)d_in[0];
    const void*  knn    = d_in[1];
    const float* w_mlp1 = (const float*)d_in[2];
    const float* b_mlp1 = (const float*)d_in[3];
    const float* w_lfa1 = (const float*)d_in[4];
    const float* b_lfa1 = (const float*)d_in[5];
    const float* w_lfa2 = (const float*)d_in[6];
    const float* b_lfa2 = (const float*)d_in[7];
    const float* w_mlp2 = (const float*)d_in[8];
    const float* b_mlp2 = (const float*)d_in[9];
    const float* w_res  = (const float*)d_in[10];
    const float* b_res  = (const float*)d_in[11];
    float* out = (float*)d_out;

    // knn dtype detection + conversion, then per-launch constants
    k_detect<<<1, 256>>>(knn);
    k_cvt<<<(NPTS * KNB) / 256, 256>>>(knn);
    k_prep<<<NPTS / 256, 256>>>(inputs);
    k_smallg<<<(NPTS * 96) / 256 + 1, 256>>>(w_lfa1, b_lfa1, w_lfa2, b_lfa2,
                                             w_mlp2, b_mlp1, b_mlp2, b_res);
    k_gather<<<(NPTS * 32) / 256, 256>>>(0);               // A(G1) -> Gcat[:,256:384]
    dim3 gC0(128, 4);
    k_gemmC0<<<gC0, 256>>>(w_mlp2);                        // C0 and f1 (block 0 folded)

    // 3 dynamic residual blocks
    int fsel = 0;  // f currently in d_fa
    for (int it = 0; it < 3; it++) {
        dim3 g1(128, 5);
        k_gemm1<<<g1, 256>>>(fsel, w_mlp1, b_mlp1, w_res); // x1 | f@w_res^T
        k_gather<<<(NPTS * 32) / 256, 256>>>(1);           // ax1 = A(x1)
        k_gather<<<(NPTS * 32) / 256, 256>>>(2);           // aax1 = A(ax1)
        dim3 g2(128, 4);
        int dsel = (it == 2) ? 2 : (fsel == 0 ? 0 : 1);
        k_gemm2<<<g2, 256>>>(fsel, dsel, w_mlp2, out);
        fsel ^= 1;
    }
    (void)in_sizes; (void)n_in; (void)out_size;
}

// round 4
// speedup vs baseline: 2.0500x; 2.0500x over previous
#include <cuda_runtime.h>
#include <cuda_bf16.h>
#include <math.h>

#define NPTS 16384
#define KNB  16

// ---------------- device scratch (static: no allocations allowed) ----------------
__device__ float d_geo[NPTS * 4];
__device__ int   d_knn32[NPTS * KNB];
__device__ int   d_knn_bad;                  // 0 => int64 knn, nonzero => int32
__device__ float d_G1[NPTS * 128];
__device__ float d_Gcat[(size_t)NPTS * 384]; // [G2 (256) | A(G1) (128)]
__device__ float d_C0[(size_t)NPTS * 512];
__device__ float d_fa[(size_t)NPTS * 512];
__device__ float d_fb[(size_t)NPTS * 512];
__device__ float d_xr[(size_t)NPTS * 640];   // [x1 (128) | f @ w_res^T (512)]
__device__ float d_ax1[NPTS * 128];
__device__ float d_aax1[NPTS * 128];
__device__ float d_dv[512];
__device__ float d_bsum[512];

// ---------------- knn dtype detection ----------------
__global__ void k_detect(const void* __restrict__ knn) {
    const long long* p = (const long long*)knn;
    const int total = NPTS * KNB / 2;
    int local = 0;
    for (int i = blockIdx.x * blockDim.x + threadIdx.x; i < total; i += gridDim.x * blockDim.x) {
        long long v = p[i];
        if (v < 0 || v >= NPTS) local = 1;
    }
    if (local) atomicOr(&d_knn_bad, 1);
}

__global__ void k_cvt(const void* __restrict__ knn) {
    int i = blockIdx.x * blockDim.x + threadIdx.x;
    if (i >= NPTS * KNB) return;
    if (d_knn_bad)
        d_knn32[i] = ((const int*)knn)[i];
    else
        d_knn32[i] = (int)((const long long*)knn)[i];
}

// ---------------- prep: geo mean ----------------
__global__ void k_prep(const float* __restrict__ inp) {
    int n = blockIdx.x * blockDim.x + threadIdx.x;
    if (n >= NPTS) return;
    float xi = inp[3 * n + 0], yi = inp[3 * n + 1], zi = inp[3 * n + 2];
    float sx = 0.f, sy = 0.f, sz = 0.f, sn = 0.f;
#pragma unroll
    for (int k = 0; k < KNB; k++) {
        int j = d_knn32[n * KNB + k];
        float dx = xi - inp[3 * j + 0];
        float dy = yi - inp[3 * j + 1];
        float dz = zi - inp[3 * j + 2];
        sx += dx; sy += dy; sz += dz;
        sn += sqrtf(dx * dx + dy * dy + dz * dz);
    }
    const float s = 1.0f / KNB;
    d_geo[n * 4 + 0] = sx * s;
    d_geo[n * 4 + 1] = sy * s;
    d_geo[n * 4 + 2] = sz * s;
    d_geo[n * 4 + 3] = sn * s;
}

// ---------------- tiny geo linears (warp/point, smem weights) + vec tail ----------------
__global__ void __launch_bounds__(256) k_smallg(
        const float* __restrict__ w_lfa1, const float* __restrict__ b_lfa1,
        const float* __restrict__ w_lfa2, const float* __restrict__ b_lfa2,
        const float* __restrict__ w_mlp2, const float* __restrict__ b_mlp1,
        const float* __restrict__ b_mlp2, const float* __restrict__ b_res) {
    int tid = threadIdx.x;
    if (blockIdx.x == 2048) {            // vector precompute tail block
        int j = tid * 2;
        if (j < 512) {
#pragma unroll
            for (int t = 0; t < 2; t++) {
                int jj = j + t;
                d_bsum[jj] = b_mlp2[jj] + b_res[jj];
                float s = 0.f;
#pragma unroll 8
                for (int c = 0; c < 128; c++) s += w_mlp2[jj * 512 + 384 + c] * b_mlp1[c];
                d_dv[jj] = s;
            }
        }
        return;
    }
    __shared__ float s_w2[256 * 4], s_b2[256], s_w1[128 * 4], s_b1[128];
    for (int i = tid; i < 1024; i += 256) s_w2[i] = w_lfa2[i];
    for (int i = tid; i < 512;  i += 256) s_w1[i] = w_lfa1[i];
    for (int i = tid; i < 256;  i += 256) s_b2[i] = b_lfa2[i];
    for (int i = tid; i < 128;  i += 256) if (i < 128) s_b1[i] = b_lfa1[i];
    __syncthreads();
    int wid = tid >> 5, lane = tid & 31;
    int n = blockIdx.x * 8 + wid;
    float4 g = *(const float4*)(d_geo + n * 4);
#pragma unroll
    for (int t = 0; t < 2; t++) {
        int j0 = t * 128 + lane * 4;
        float r[4];
#pragma unroll
        for (int u = 0; u < 4; u++) {
            int j = j0 + u;
            r[u] = s_b2[j] + g.x * s_w2[j * 4 + 0] + g.y * s_w2[j * 4 + 1]
                           + g.z * s_w2[j * 4 + 2] + g.w * s_w2[j * 4 + 3];
        }
        *(float4*)(d_Gcat + (size_t)n * 384 + j0) = make_float4(r[0], r[1], r[2], r[3]);
    }
    {
        int j0 = lane * 4;
        float r[4];
#pragma unroll
        for (int u = 0; u < 4; u++) {
            int j = j0 + u;
            r[u] = s_b1[j] + g.x * s_w1[j * 4 + 0] + g.y * s_w1[j * 4 + 1]
                           + g.z * s_w1[j * 4 + 2] + g.w * s_w1[j * 4 + 3];
        }
        *(float4*)(d_G1 + (size_t)n * 128 + j0) = make_float4(r[0], r[1], r[2], r[3]);
    }
}

// ---------------- gather-mean (d = 128), one warp per point ----------------
__global__ void __launch_bounds__(256) k_gather(int mode) {
    int t = blockIdx.x * blockDim.x + threadIdx.x;
    int n = t >> 5;
    if (n >= NPTS) return;
    int lane = t & 31;
    const float* src; float* dst; int sld, dld, doff;
    if (mode == 0)      { src = d_G1;  sld = 128; dst = d_Gcat; dld = 384; doff = 256; }
    else if (mode == 1) { src = d_xr;  sld = 640; dst = d_ax1;  dld = 128; doff = 0; }
    else                { src = d_ax1; sld = 128; dst = d_aax1; dld = 128; doff = 0; }
    const int* kn = d_knn32 + n * KNB;
    float ax = 0.f, ay = 0.f, az = 0.f, aw = 0.f;
#pragma unroll
    for (int k = 0; k < KNB; k++) {
        int j = kn[k];
        float4 v = *(const float4*)(src + (size_t)j * sld + lane * 4);
        ax += v.x; ay += v.y; az += v.z; aw += v.w;
    }
    const float s = 1.0f / KNB;
    *(float4*)(dst + (size_t)n * dld + doff + lane * 4) =
        make_float4(ax * s, ay * s, az * s, aw * s);
}

// ================= bf16x3 tensor-core GEMM core =================
// Tile 128x128x32, 256 threads = 8 warps (4 along M, 2 along N).
// Warp tile 32x64: m-atoms 2 (m16), n-atoms 8 (n8), k16 mma, fp32 accum.
// A[M,K] row-major fp32, B[N,K] row-major fp32 (weights). D = A @ B^T.
#define ASTR 40   // smem row stride in bf16 elems (32 + 8 pad -> conflict-free)

__device__ __forceinline__ void mma16816(float* c, const unsigned* a, unsigned b0, unsigned b1) {
    asm volatile(
        "mma.sync.aligned.m16n8k16.row.col.f32.bf16.bf16.f32 "
        "{%0,%1,%2,%3}, {%4,%5,%6,%7}, {%8,%9}, {%0,%1,%2,%3};"
        : "+f"(c[0]), "+f"(c[1]), "+f"(c[2]), "+f"(c[3])
        : "r"(a[0]), "r"(a[1]), "r"(a[2]), "r"(a[3]), "r"(b0), "r"(b1));
}

__device__ __forceinline__ void cvt_hl(float x, __nv_bfloat16& h, __nv_bfloat16& l) {
    h = __float2bfloat16(x);
    l = __float2bfloat16(x - __bfloat162float(h));
}

// acc[mi][ni][4]
__device__ __forceinline__ void gemm_mma(const float* __restrict__ A, int lda,
                                         const float* __restrict__ B, int ldb,
                                         int K, float (&acc)[2][8][4]) {
    __shared__ __nv_bfloat16 sAh[128 * ASTR], sAl[128 * ASTR];
    __shared__ __nv_bfloat16 sBh[128 * ASTR], sBl[128 * ASTR];
    const int tid = threadIdx.x;
    const int lane = tid & 31, wid = tid >> 5;
    const int warp_m = wid & 3, warp_n = wid >> 2;
    const int grp = lane >> 2, tig = lane & 3;

    for (int k0 = 0; k0 < K; k0 += 32) {
        __syncthreads();
        // load 128x32 fp32 of A and B, split into bf16 hi/lo
#pragma unroll
        for (int i = 0; i < 4; i++) {
            int idx = tid + i * 256;          // 0..1023
            int r = idx >> 3;
            int c = (idx & 7) * 4;
            float4 va = *(const float4*)(A + (size_t)r * lda + k0 + c);
            float4 vb = *(const float4*)(B + (size_t)r * ldb + k0 + c);
            __nv_bfloat16 h0, l0, h1, l1, h2, l2, h3, l3;
            cvt_hl(va.x, h0, l0); cvt_hl(va.y, h1, l1);
            cvt_hl(va.z, h2, l2); cvt_hl(va.w, h3, l3);
            *(__nv_bfloat162*)(sAh + r * ASTR + c)     = __nv_bfloat162(h0, h1);
            *(__nv_bfloat162*)(sAh + r * ASTR + c + 2) = __nv_bfloat162(h2, h3);
            *(__nv_bfloat162*)(sAl + r * ASTR + c)     = __nv_bfloat162(l0, l1);
            *(__nv_bfloat162*)(sAl + r * ASTR + c + 2) = __nv_bfloat162(l2, l3);
            cvt_hl(vb.x, h0, l0); cvt_hl(vb.y, h1, l1);
            cvt_hl(vb.z, h2, l2); cvt_hl(vb.w, h3, l3);
            *(__nv_bfloat162*)(sBh + r * ASTR + c)     = __nv_bfloat162(h0, h1);
            *(__nv_bfloat162*)(sBh + r * ASTR + c + 2) = __nv_bfloat162(h2, h3);
            *(__nv_bfloat162*)(sBl + r * ASTR + c)     = __nv_bfloat162(l0, l1);
            *(__nv_bfloat162*)(sBl + r * ASTR + c + 2) = __nv_bfloat162(l2, l3);
        }
        __syncthreads();
#pragma unroll
        for (int ks = 0; ks < 32; ks += 16) {
            unsigned ah[2][4], al[2][4];
#pragma unroll
            for (int mi = 0; mi < 2; mi++) {
                int r = warp_m * 32 + mi * 16 + grp;
                const __nv_bfloat16* ph = sAh + r * ASTR + ks + 2 * tig;
                const __nv_bfloat16* pl = sAl + r * ASTR + ks + 2 * tig;
                ah[mi][0] = *(const unsigned*)(ph);
                ah[mi][1] = *(const unsigned*)(ph + 8 * ASTR);
                ah[mi][2] = *(const unsigned*)(ph + 8);
                ah[mi][3] = *(const unsigned*)(ph + 8 * ASTR + 8);
                al[mi][0] = *(const unsigned*)(pl);
                al[mi][1] = *(const unsigned*)(pl + 8 * ASTR);
                al[mi][2] = *(const unsigned*)(pl + 8);
                al[mi][3] = *(const unsigned*)(pl + 8 * ASTR + 8);
            }
#pragma unroll
            for (int ni = 0; ni < 8; ni++) {
                int r = warp_n * 64 + ni * 8 + grp;
                const __nv_bfloat16* ph = sBh + r * ASTR + ks + 2 * tig;
                const __nv_bfloat16* pl = sBl + r * ASTR + ks + 2 * tig;
                unsigned bh0 = *(const unsigned*)(ph);
                unsigned bh1 = *(const unsigned*)(ph + 8);
                unsigned bl0 = *(const unsigned*)(pl);
                unsigned bl1 = *(const unsigned*)(pl + 8);
#pragma unroll
                for (int mi = 0; mi < 2; mi++) {
                    mma16816(acc[mi][ni], ah[mi], bh0, bh1);
                    mma16816(acc[mi][ni], ah[mi], bl0, bl1);
                    mma16816(acc[mi][ni], al[mi], bh0, bh1);
                }
            }
        }
    }
}

// output coordinates helper: rows r0, r0+8 ; cols cc, cc+1 per (mi, ni)
#define EPILOG_COORDS() \
    const int lane = threadIdx.x & 31, wid = threadIdx.x >> 5; \
    const int warp_m = wid & 3, warp_n = wid >> 2; \
    const int grp = lane >> 2, tig = lane & 3;

// ---------------- GEMM C0: Gcat[N,384] @ W2[:, :384]^T + bsum ; fa = C0 + dv ----------------
__global__ void __launch_bounds__(256, 2) k_gemmC0(const float* __restrict__ w_mlp2) {
    float acc[2][8][4] = {};
    gemm_mma(d_Gcat + (size_t)blockIdx.x * 128 * 384, 384,
             w_mlp2 + (size_t)blockIdx.y * 128 * 512, 512, 384, acc);
    EPILOG_COORDS();
#pragma unroll
    for (int mi = 0; mi < 2; mi++) {
#pragma unroll
        for (int ni = 0; ni < 8; ni++) {
            int r0 = blockIdx.x * 128 + warp_m * 32 + mi * 16 + grp;
            int cc = blockIdx.y * 128 + warp_n * 64 + ni * 8 + tig * 2;
            float2 bs = *(const float2*)(d_bsum + cc);
            float2 dv = *(const float2*)(d_dv + cc);
            float* a = acc[mi][ni];
            float2 c0 = make_float2(a[0] + bs.x, a[1] + bs.y);
            float2 c1 = make_float2(a[2] + bs.x, a[3] + bs.y);
            size_t o0 = (size_t)r0 * 512 + cc, o1 = (size_t)(r0 + 8) * 512 + cc;
            *(float2*)(d_C0 + o0) = c0;
            *(float2*)(d_C0 + o1) = c1;
            *(float2*)(d_fa + o0) = make_float2(c0.x + dv.x, c0.y + dv.y);
            *(float2*)(d_fa + o1) = make_float2(c1.x + dv.x, c1.y + dv.y);
        }
    }
}

// ---------------- GEMM1: xr = f @ [w_mlp1 ; w_res]^T  (N=640, K=512) ----------------
__global__ void __launch_bounds__(256, 2) k_gemm1(int fsel,
        const float* __restrict__ w_mlp1, const float* __restrict__ b_mlp1,
        const float* __restrict__ w_res) {
    const float* f = fsel ? d_fb : d_fa;
    const float* B = (blockIdx.y == 0) ? w_mlp1
                                       : (w_res + (size_t)(blockIdx.y - 1) * 128 * 512);
    float acc[2][8][4] = {};
    gemm_mma(f + (size_t)blockIdx.x * 128 * 512, 512, B, 512, 512, acc);
    EPILOG_COORDS();
#pragma unroll
    for (int mi = 0; mi < 2; mi++) {
#pragma unroll
        for (int ni = 0; ni < 8; ni++) {
            int r0 = blockIdx.x * 128 + warp_m * 32 + mi * 16 + grp;
            int cc = blockIdx.y * 128 + warp_n * 64 + ni * 8 + tig * 2;
            float2 bs = make_float2(0.f, 0.f);
            if (blockIdx.y == 0) bs = *(const float2*)(b_mlp1 + (cc & 127));
            float* a = acc[mi][ni];
            *(float2*)(d_xr + (size_t)r0 * 640 + cc)       = make_float2(a[0] + bs.x, a[1] + bs.y);
            *(float2*)(d_xr + (size_t)(r0 + 8) * 640 + cc) = make_float2(a[2] + bs.x, a[3] + bs.y);
        }
    }
}

// ---------------- GEMM2: f_new = C0 + f + r + aax1 @ W2[:,384:512]^T  (K=128) ----------------
__global__ void __launch_bounds__(256, 2) k_gemm2(int fsel, int dsel,
        const float* __restrict__ w_mlp2, float* __restrict__ outp) {
    const float* f = fsel ? d_fb : d_fa;
    float* dst = (dsel == 0) ? d_fb : (dsel == 1) ? d_fa : outp;
    float acc[2][8][4] = {};
    gemm_mma(d_aax1 + (size_t)blockIdx.x * 128 * 128, 128,
             w_mlp2 + (size_t)blockIdx.y * 128 * 512 + 384, 512, 128, acc);
    EPILOG_COORDS();
#pragma unroll
    for (int mi = 0; mi < 2; mi++) {
#pragma unroll
        for (int ni = 0; ni < 8; ni++) {
            int r0 = blockIdx.x * 128 + warp_m * 32 + mi * 16 + grp;
            int cc = blockIdx.y * 128 + warp_n * 64 + ni * 8 + tig * 2;
            float* a = acc[mi][ni];
#pragma unroll
            for (int h = 0; h < 2; h++) {
                int r = r0 + h * 8;
                size_t o = (size_t)r * 512 + cc;
                float2 c0 = *(const float2*)(d_C0 + o);
                float2 fv = *(const float2*)(f + o);
                float2 rv = *(const float2*)(d_xr + (size_t)r * 640 + 128 + cc);
                *(float2*)(dst + o) = make_float2(a[2 * h + 0] + c0.x + fv.x + rv.x,
                                                  a[2 * h + 1] + c0.y + fv.y + rv.y);
            }
        }
    }
}

// ---------------- launch ----------------
extern "C" void kernel_launch(void* const* d_in, const int* in_sizes, int n_in,
                              void* d_out, int out_size) {
    const float* inputs = (const float*)d_in[0];
    const void*  knn    = d_in[1];
    const float* w_mlp1 = (const float*)d_in[2];
    const float* b_mlp1 = (const float*)d_in[3];
    const float* w_lfa1 = (const float*)d_in[4];
    const float* b_lfa1 = (const float*)d_in[5];
    const float* w_lfa2 = (const float*)d_in[6];
    const float* b_lfa2 = (const float*)d_in[7];
    const float* w_mlp2 = (const float*)d_in[8];
    const float* b_mlp2 = (const float*)d_in[9];
    const float* w_res  = (const float*)d_in[10];
    const float* b_res  = (const float*)d_in[11];
    float* out = (float*)d_out;

    k_detect<<<128, 256>>>(knn);
    k_cvt<<<(NPTS * KNB) / 256, 256>>>(knn);
    k_prep<<<NPTS / 256, 256>>>(inputs);
    k_smallg<<<2049, 256>>>(w_lfa1, b_lfa1, w_lfa2, b_lfa2,
                            w_mlp2, b_mlp1, b_mlp2, b_res);
    k_gather<<<(NPTS * 32) / 256, 256>>>(0);
    dim3 gC0(128, 4);
    k_gemmC0<<<gC0, 256>>>(w_mlp2);

    int fsel = 0;
    for (int it = 0; it < 3; it++) {
        dim3 g1(128, 5);
        k_gemm1<<<g1, 256>>>(fsel, w_mlp1, b_mlp1, w_res);
        k_gather<<<(NPTS * 32) / 256, 256>>>(1);
        k_gather<<<(NPTS * 32) / 256, 256>>>(2);
        dim3 g2(128, 4);
        int dsel = (it == 2) ? 2 : (fsel == 0 ? 0 : 1);
        k_gemm2<<<g2, 256>>>(fsel, dsel, w_mlp2, out);
        fsel ^= 1;
    }
    (void)in_sizes; (void)n_in; (void)out_size;
}